// round 5
// baseline (speedup 1.0000x reference)
#include <cuda_runtime.h>

#define NN 500000
#define NE 8000000
#define TPB 256

// ---------------- scratch (static __device__ — no allocation) ----------------
__device__ float  g_degf[NN];
__device__ float  g_dsr [NN];   // deg^-1/2
__device__ float  g_dinv[NN];   // deg^-1
__device__ float  g_xs  [NN];   // input feature (scalar)
__device__ float  g_norm[NE];   // per-edge norm = dsr[src]*dsr[dst]
__device__ float  g_agg1[NN];          // layer1 aggregate (F=1)
__device__ float4 g_h1  [NN];          // layer1 output  (F=4)
__device__ float4 g_agg2[NN];          // layer2 aggregate (F=4)
__device__ float4 g_h2  [2 * NN];      // layer2 output  (F=8)
__device__ float4 g_agg3[2 * NN];      // layer3 aggregate (F=8)
__device__ float4 g_h3  [4 * NN];      // layer3 output  (F=16)
__device__ float4 g_agg4[4 * NN];      // layer4 aggregate (F=16)

// ---------------- weights in constant memory ----------------
// layout: W1[4] b1[4] W2[32] b2[8] W3[128] b3[16] W4[512] b4[32] = 736 floats
__constant__ float c_w[736];
#define W1_OFF 0
#define B1_OFF 4
#define W2_OFF 8
#define B2_OFF 40
#define W3_OFF 48
#define B3_OFF 176
#define W4_OFF 192
#define B4_OFF 704

// ---------------- vector reductions (sm_90+: red.global.add.v4.f32) ----------------
__device__ __forceinline__ void red_add(float* a, float v) {
    asm volatile("red.global.add.f32 [%0], %1;" :: "l"(a), "f"(v) : "memory");
}
__device__ __forceinline__ void red_add4(float* a, float x, float y, float z, float w) {
    asm volatile("red.global.add.v4.f32 [%0], {%1, %2, %3, %4};"
                 :: "l"(a), "f"(x), "f"(y), "f"(z), "f"(w) : "memory");
}

// ---------------- kernels ----------------
__global__ void k_zero() {
    int i = blockIdx.x * TPB + threadIdx.x;
    if (i < NN) g_degf[i] = 0.f;
}

__global__ void k_deg(const int* __restrict__ dst) {
    int e = blockIdx.x * TPB + threadIdx.x;
    if (e < NE) red_add(&g_degf[dst[e]], 1.0f);
}

__global__ void k_node1(const int* __restrict__ rl) {
    int i = blockIdx.x * TPB + threadIdx.x;
    if (i >= NN) return;
    float deg = g_degf[i] + 1.0f;
    float ds  = rsqrtf(deg);
    float di  = 1.0f / deg;
    float x   = (float)rl[i] * (1.0f / 20000.0f);
    g_dsr[i]  = ds;
    g_dinv[i] = di;
    g_xs[i]   = x;
    g_agg1[i] = x * di;          // self-loop term pre-added
}

// layer-1 edge pass (F=1), also produces norm_e for later layers
__global__ void k_edge1(const int* __restrict__ src, const int* __restrict__ dst) {
    int e = blockIdx.x * TPB + threadIdx.x;
    if (e >= NE) return;
    int s = src[e], d = dst[e];
    float w = g_dsr[s] * g_dsr[d];
    g_norm[e] = w;
    red_add(&g_agg1[d], g_xs[s] * w);
}

// h1 = y1*W1 + b1 ; init agg2 with self-loop term
__global__ void k_node2() {
    int i = blockIdx.x * TPB + threadIdx.x;
    if (i >= NN) return;
    float y  = g_agg1[i];
    float di = g_dinv[i];
    float4 h;
    h.x = fmaf(y, c_w[W1_OFF + 0], c_w[B1_OFF + 0]);
    h.y = fmaf(y, c_w[W1_OFF + 1], c_w[B1_OFF + 1]);
    h.z = fmaf(y, c_w[W1_OFF + 2], c_w[B1_OFF + 2]);
    h.w = fmaf(y, c_w[W1_OFF + 3], c_w[B1_OFF + 3]);
    g_h1[i]   = h;
    g_agg2[i] = make_float4(h.x * di, h.y * di, h.z * di, h.w * di);
}

// layer-2 edge pass (F=4)
__global__ void k_edge2(const int* __restrict__ src, const int* __restrict__ dst) {
    int e = blockIdx.x * TPB + threadIdx.x;
    if (e >= NE) return;
    int s = src[e], d = dst[e];
    float w = g_norm[e];
    float4 h = g_h1[s];
    red_add4((float*)(g_agg2 + d), h.x * w, h.y * w, h.z * w, h.w * w);
}

// h2 = y2@W2 + b2 (4->8) ; init agg3
__global__ void k_node3() {
    int i = blockIdx.x * TPB + threadIdx.x;
    if (i >= NN) return;
    float4 y  = g_agg2[i];
    float di  = g_dinv[i];
    float h[8];
#pragma unroll
    for (int j = 0; j < 8; j++) {
        float a = c_w[B2_OFF + j];
        a = fmaf(y.x, c_w[W2_OFF +  0 + j], a);
        a = fmaf(y.y, c_w[W2_OFF +  8 + j], a);
        a = fmaf(y.z, c_w[W2_OFF + 16 + j], a);
        a = fmaf(y.w, c_w[W2_OFF + 24 + j], a);
        h[j] = a;
    }
    g_h2[2 * i]     = make_float4(h[0], h[1], h[2], h[3]);
    g_h2[2 * i + 1] = make_float4(h[4], h[5], h[6], h[7]);
    g_agg3[2 * i]     = make_float4(h[0] * di, h[1] * di, h[2] * di, h[3] * di);
    g_agg3[2 * i + 1] = make_float4(h[4] * di, h[5] * di, h[6] * di, h[7] * di);
}

// layer-3 edge pass (F=8)
__global__ void k_edge3(const int* __restrict__ src, const int* __restrict__ dst) {
    int e = blockIdx.x * TPB + threadIdx.x;
    if (e >= NE) return;
    int s = src[e], d = dst[e];
    float w = g_norm[e];
    float4 a = g_h2[2 * s];
    float4 b = g_h2[2 * s + 1];
    red_add4((float*)(g_agg3 + 2 * d),     a.x * w, a.y * w, a.z * w, a.w * w);
    red_add4((float*)(g_agg3 + 2 * d + 1), b.x * w, b.y * w, b.z * w, b.w * w);
}

// h3 = y3@W3 + b3 (8->16) ; init agg4
__global__ void k_node4() {
    int i = blockIdx.x * TPB + threadIdx.x;
    if (i >= NN) return;
    float4 ya = g_agg3[2 * i];
    float4 yb = g_agg3[2 * i + 1];
    float y[8] = { ya.x, ya.y, ya.z, ya.w, yb.x, yb.y, yb.z, yb.w };
    float di   = g_dinv[i];
    float h[16];
#pragma unroll
    for (int j = 0; j < 16; j++) {
        float a = c_w[B3_OFF + j];
#pragma unroll
        for (int k = 0; k < 8; k++)
            a = fmaf(y[k], c_w[W3_OFF + k * 16 + j], a);
        h[j] = a;
    }
#pragma unroll
    for (int c = 0; c < 4; c++) {
        g_h3[4 * i + c]   = make_float4(h[4 * c], h[4 * c + 1], h[4 * c + 2], h[4 * c + 3]);
        g_agg4[4 * i + c] = make_float4(h[4 * c] * di, h[4 * c + 1] * di,
                                        h[4 * c + 2] * di, h[4 * c + 3] * di);
    }
}

// layer-4 edge pass (F=16)
__global__ void k_edge4(const int* __restrict__ src, const int* __restrict__ dst) {
    int e = blockIdx.x * TPB + threadIdx.x;
    if (e >= NE) return;
    int s = src[e], d = dst[e];
    float w = g_norm[e];
#pragma unroll
    for (int c = 0; c < 4; c++) {
        float4 h = g_h3[4 * s + c];
        red_add4((float*)(g_agg4 + 4 * d + c), h.x * w, h.y * w, h.z * w, h.w * w);
    }
}

// out = y4@W4 + b4 (16->32)
__global__ void k_out(float* __restrict__ out) {
    int i = blockIdx.x * TPB + threadIdx.x;
    if (i >= NN) return;
    float y[16];
#pragma unroll
    for (int c = 0; c < 4; c++) {
        float4 v = g_agg4[4 * i + c];
        y[4 * c] = v.x; y[4 * c + 1] = v.y; y[4 * c + 2] = v.z; y[4 * c + 3] = v.w;
    }
    float4* o = (float4*)(out + (size_t)i * 32);
#pragma unroll
    for (int c = 0; c < 8; c++) {
        float4 r;
        float* rp = (float*)&r;
#pragma unroll
        for (int q = 0; q < 4; q++) {
            int j = 4 * c + q;
            float a = c_w[B4_OFF + j];
#pragma unroll
            for (int k = 0; k < 16; k++)
                a = fmaf(y[k], c_w[W4_OFF + k * 32 + j], a);
            rp[q] = a;
        }
        o[c] = r;
    }
}

// ---------------- launch ----------------
extern "C" void kernel_launch(void* const* d_in, const int* in_sizes, int n_in,
                              void* d_out, int out_size) {
    const int* rl  = (const int*)d_in[0];
    const int* ei  = (const int*)d_in[1];
    const int* src = ei;
    const int* dst = ei + NE;

    // weights -> constant memory (D2D async memcpys: graph-capturable)
    cudaMemcpyToSymbolAsync(c_w, d_in[2],   4 * sizeof(float), W1_OFF * sizeof(float), cudaMemcpyDeviceToDevice, 0);
    cudaMemcpyToSymbolAsync(c_w, d_in[3],   4 * sizeof(float), B1_OFF * sizeof(float), cudaMemcpyDeviceToDevice, 0);
    cudaMemcpyToSymbolAsync(c_w, d_in[4],  32 * sizeof(float), W2_OFF * sizeof(float), cudaMemcpyDeviceToDevice, 0);
    cudaMemcpyToSymbolAsync(c_w, d_in[5],   8 * sizeof(float), B2_OFF * sizeof(float), cudaMemcpyDeviceToDevice, 0);
    cudaMemcpyToSymbolAsync(c_w, d_in[6], 128 * sizeof(float), W3_OFF * sizeof(float), cudaMemcpyDeviceToDevice, 0);
    cudaMemcpyToSymbolAsync(c_w, d_in[7],  16 * sizeof(float), B3_OFF * sizeof(float), cudaMemcpyDeviceToDevice, 0);
    cudaMemcpyToSymbolAsync(c_w, d_in[8], 512 * sizeof(float), W4_OFF * sizeof(float), cudaMemcpyDeviceToDevice, 0);
    cudaMemcpyToSymbolAsync(c_w, d_in[9],  32 * sizeof(float), B4_OFF * sizeof(float), cudaMemcpyDeviceToDevice, 0);

    const int nb_n = (NN + TPB - 1) / TPB;
    const int nb_e = (NE + TPB - 1) / TPB;

    k_zero <<<nb_n, TPB>>>();
    k_deg  <<<nb_e, TPB>>>(dst);
    k_node1<<<nb_n, TPB>>>(rl);
    k_edge1<<<nb_e, TPB>>>(src, dst);
    k_node2<<<nb_n, TPB>>>();
    k_edge2<<<nb_e, TPB>>>(src, dst);
    k_node3<<<nb_n, TPB>>>();
    k_edge3<<<nb_e, TPB>>>(src, dst);
    k_node4<<<nb_n, TPB>>>();
    k_edge4<<<nb_e, TPB>>>(src, dst);
    k_out  <<<nb_n, TPB>>>((float*)d_out);
}

// round 7
// speedup vs baseline: 1.3730x; 1.3730x over previous
#include <cuda_runtime.h>

#define NN 500000
#define NE 8000000
#define TPB 256

// ---------------- scratch (static __device__ — no allocation) ----------------
__device__ float  g_degf[NN];
__device__ float  g_dsr [NN];        // (deg+1)^-1/2
__device__ float  g_s0  [NN];        // layer-0 scaled feature  x*dsr   (gather src)
__device__ float  g_a0  [NN];        // layer-0 accumulator (init = s0, RED target)
__device__ float4 g_s1  [NN];        // F=4  scaled h1*dsr
__device__ float4 g_a1  [NN];
__device__ float4 g_s2  [2 * NN];    // F=8
__device__ float4 g_a2  [2 * NN];
__device__ float4 g_s3  [4 * NN];    // F=16
__device__ float4 g_a3  [4 * NN];

// ---------------- weights in constant memory ----------------
// layout: W1[4] b1[4] W2[32] b2[8] W3[128] b3[16] W4[512] b4[32] = 736 floats
__constant__ float c_w[736];
#define W1_OFF 0
#define B1_OFF 4
#define W2_OFF 8
#define B2_OFF 40
#define W3_OFF 48
#define B3_OFF 176
#define W4_OFF 192
#define B4_OFF 704

// ---------------- vector reductions ----------------
__device__ __forceinline__ void red_add(float* a, float v) {
    asm volatile("red.global.add.f32 [%0], %1;" :: "l"(a), "f"(v) : "memory");
}
__device__ __forceinline__ void red_add4(float* a, float4 v) {
    asm volatile("red.global.add.v4.f32 [%0], {%1, %2, %3, %4};"
                 :: "l"(a), "f"(v.x), "f"(v.y), "f"(v.z), "f"(v.w) : "memory");
}

// ---------------- kernels ----------------
__global__ void k_zero() {
    int i = blockIdx.x * TPB + threadIdx.x;
    if (i < NN) g_degf[i] = 0.f;
}

__global__ void k_deg(const int* __restrict__ dst) {
    int e = blockIdx.x * TPB + threadIdx.x;
    if (e < NE) red_add(&g_degf[dst[e]], 1.0f);
}

// deg -> dsr ; s0 = x*dsr ; a0 = s0 (self term folded in)
__global__ void k_node1(const int* __restrict__ rl) {
    int i = blockIdx.x * TPB + threadIdx.x;
    if (i >= NN) return;
    float deg = g_degf[i] + 1.0f;
    float ds  = rsqrtf(deg);
    float hs  = (float)rl[i] * (1.0f / 20000.0f) * ds;
    g_dsr[i] = ds;
    g_s0[i]  = hs;
    g_a0[i]  = hs;
}

// F=1 edge pass: pure gather + RED
__global__ void k_edge0(const int* __restrict__ src, const int* __restrict__ dst) {
    int e = blockIdx.x * TPB + threadIdx.x;
    if (e >= NE) return;
    red_add(&g_a0[dst[e]], g_s0[src[e]]);
}

// z = dsr*a0 ; h = z*W1 + b1 (1->4) ; s1 = h*dsr ; a1 = s1
__global__ void k_node2() {
    int i = blockIdx.x * TPB + threadIdx.x;
    if (i >= NN) return;
    float ds = g_dsr[i];
    float z  = ds * g_a0[i];
    float4 h;
    h.x = fmaf(z, c_w[W1_OFF + 0], c_w[B1_OFF + 0]) * ds;
    h.y = fmaf(z, c_w[W1_OFF + 1], c_w[B1_OFF + 1]) * ds;
    h.z = fmaf(z, c_w[W1_OFF + 2], c_w[B1_OFF + 2]) * ds;
    h.w = fmaf(z, c_w[W1_OFF + 3], c_w[B1_OFF + 3]) * ds;
    g_s1[i] = h;
    g_a1[i] = h;
}

// F=4 edge pass
__global__ void k_edge1(const int* __restrict__ src, const int* __restrict__ dst) {
    int e = blockIdx.x * TPB + threadIdx.x;
    if (e >= NE) return;
    float4 v = g_s1[src[e]];
    red_add4((float*)(g_a1 + dst[e]), v);
}

// z = dsr*a1 ; h = z@W2 + b2 (4->8) ; s2 = h*dsr ; a2 = s2
__global__ void k_node3() {
    int i = blockIdx.x * TPB + threadIdx.x;
    if (i >= NN) return;
    float ds = g_dsr[i];
    float4 a = g_a1[i];
    float z[4] = { ds * a.x, ds * a.y, ds * a.z, ds * a.w };
    float h[8];
#pragma unroll
    for (int j = 0; j < 8; j++) {
        float t = c_w[B2_OFF + j];
#pragma unroll
        for (int k = 0; k < 4; k++)
            t = fmaf(z[k], c_w[W2_OFF + k * 8 + j], t);
        h[j] = t * ds;
    }
    float4 v0 = make_float4(h[0], h[1], h[2], h[3]);
    float4 v1 = make_float4(h[4], h[5], h[6], h[7]);
    g_s2[2 * i]     = v0;  g_s2[2 * i + 1] = v1;
    g_a2[2 * i]     = v0;  g_a2[2 * i + 1] = v1;
}

// F=8 edge pass, 2 lanes per edge: one LDG.128 + one RED.v4 per lane
__global__ void k_edge2(const int* __restrict__ src, const int* __restrict__ dst) {
    int t = blockIdx.x * TPB + threadIdx.x;
    int e = t >> 1;
    if (e >= NE) return;
    int p = t & 1;
    float4 v = g_s2[2 * src[e] + p];
    red_add4((float*)(g_a2 + 2 * dst[e] + p), v);
}

// z = dsr*a2 ; h = z@W3 + b3 (8->16) ; s3 = h*dsr ; a3 = s3
__global__ void k_node4() {
    int i = blockIdx.x * TPB + threadIdx.x;
    if (i >= NN) return;
    float ds = g_dsr[i];
    float4 a0 = g_a2[2 * i];
    float4 a1 = g_a2[2 * i + 1];
    float z[8] = { ds*a0.x, ds*a0.y, ds*a0.z, ds*a0.w,
                   ds*a1.x, ds*a1.y, ds*a1.z, ds*a1.w };
    float h[16];
#pragma unroll
    for (int j = 0; j < 16; j++) {
        float t = c_w[B3_OFF + j];
#pragma unroll
        for (int k = 0; k < 8; k++)
            t = fmaf(z[k], c_w[W3_OFF + k * 16 + j], t);
        h[j] = t * ds;
    }
#pragma unroll
    for (int c = 0; c < 4; c++) {
        float4 v = make_float4(h[4*c], h[4*c+1], h[4*c+2], h[4*c+3]);
        g_s3[4 * i + c] = v;
        g_a3[4 * i + c] = v;
    }
}

// F=16 edge pass, 4 lanes per edge
__global__ void k_edge3(const int* __restrict__ src, const int* __restrict__ dst) {
    long long t = (long long)blockIdx.x * TPB + threadIdx.x;
    int e = (int)(t >> 2);
    if (e >= NE) return;
    int p = (int)(t & 3);
    float4 v = g_s3[4 * src[e] + p];
    red_add4((float*)(g_a3 + 4 * dst[e] + p), v);
}

// z = dsr*a3 ; out = z@W4 + b4 (16->32)
__global__ void k_out(float* __restrict__ out) {
    int i = blockIdx.x * TPB + threadIdx.x;
    if (i >= NN) return;
    float ds = g_dsr[i];
    float z[16];
#pragma unroll
    for (int c = 0; c < 4; c++) {
        float4 v = g_a3[4 * i + c];
        z[4*c] = ds*v.x; z[4*c+1] = ds*v.y; z[4*c+2] = ds*v.z; z[4*c+3] = ds*v.w;
    }
    float4* o = (float4*)(out + (size_t)i * 32);
#pragma unroll
    for (int c = 0; c < 8; c++) {
        float4 r;
        float* rp = (float*)&r;
#pragma unroll
        for (int q = 0; q < 4; q++) {
            int j = 4 * c + q;
            float t = c_w[B4_OFF + j];
#pragma unroll
            for (int k = 0; k < 16; k++)
                t = fmaf(z[k], c_w[W4_OFF + k * 32 + j], t);
            rp[q] = t;
        }
        o[c] = r;
    }
}

// ---------------- launch ----------------
extern "C" void kernel_launch(void* const* d_in, const int* in_sizes, int n_in,
                              void* d_out, int out_size) {
    const int* rl  = (const int*)d_in[0];
    const int* ei  = (const int*)d_in[1];
    const int* src = ei;
    const int* dst = ei + NE;

    cudaMemcpyToSymbolAsync(c_w, d_in[2],   4 * sizeof(float), W1_OFF * sizeof(float), cudaMemcpyDeviceToDevice, 0);
    cudaMemcpyToSymbolAsync(c_w, d_in[3],   4 * sizeof(float), B1_OFF * sizeof(float), cudaMemcpyDeviceToDevice, 0);
    cudaMemcpyToSymbolAsync(c_w, d_in[4],  32 * sizeof(float), W2_OFF * sizeof(float), cudaMemcpyDeviceToDevice, 0);
    cudaMemcpyToSymbolAsync(c_w, d_in[5],   8 * sizeof(float), B2_OFF * sizeof(float), cudaMemcpyDeviceToDevice, 0);
    cudaMemcpyToSymbolAsync(c_w, d_in[6], 128 * sizeof(float), W3_OFF * sizeof(float), cudaMemcpyDeviceToDevice, 0);
    cudaMemcpyToSymbolAsync(c_w, d_in[7],  16 * sizeof(float), B3_OFF * sizeof(float), cudaMemcpyDeviceToDevice, 0);
    cudaMemcpyToSymbolAsync(c_w, d_in[8], 512 * sizeof(float), W4_OFF * sizeof(float), cudaMemcpyDeviceToDevice, 0);
    cudaMemcpyToSymbolAsync(c_w, d_in[9],  32 * sizeof(float), B4_OFF * sizeof(float), cudaMemcpyDeviceToDevice, 0);

    const int nb_n  = (NN + TPB - 1) / TPB;
    const int nb_e  = (NE + TPB - 1) / TPB;
    const int nb_e2 = (2 * NE + TPB - 1) / TPB;
    const int nb_e4 = (4 * NE + TPB - 1) / TPB;

    k_zero <<<nb_n,  TPB>>>();
    k_deg  <<<nb_e,  TPB>>>(dst);
    k_node1<<<nb_n,  TPB>>>(rl);
    k_edge0<<<nb_e,  TPB>>>(src, dst);
    k_node2<<<nb_n,  TPB>>>();
    k_edge1<<<nb_e,  TPB>>>(src, dst);
    k_node3<<<nb_n,  TPB>>>();
    k_edge2<<<nb_e2, TPB>>>(src, dst);
    k_node4<<<nb_n,  TPB>>>();
    k_edge3<<<nb_e4, TPB>>>(src, dst);
    k_out  <<<nb_n,  TPB>>>((float*)d_out);
}